// round 8
// baseline (speedup 1.0000x reference)
#include <cuda_runtime.h>
#include <cuda_fp16.h>
#include <cstdint>

// LSTMClassifier B=2048,T=256,F=64,H=128 via mma.sync (HMMA) on sm_103.
// 512 threads / 16 warps per block, 16 batch rows per block.
// Gate-interleaved M packing (pr = unit*4 + gate): warp-local epilogue via
// 4x4 lane butterfly transpose. One __syncthreads per step.
// x published TWO steps ahead so the W_ih x-GEMM runs as a tail overlapping
// the epilogue phase, off the h-critical path.

#define T_STEPS 256
#define FDIM 64
#define HDIM 128
#define ROWS 16
#define NBLOCKS 128
#define NTHREADS 512

// smem byte offsets
#define AW_OFF   0                        // 32 mtiles x 12 kt x 512B = 196608
#define HB_OFF   196608                   // h^T double buffer: 2 x 4096
#define XB_OFF   (HB_OFF + 8192)          // x^T double buffer: 2 x 2048
#define HS_OFF   (XB_OFF + 4096)          // final h fp32 [128 u][16 r] = 8192
#define SMEM_TOTAL (HS_OFF + 8192)        // 217088

__device__ __forceinline__ uint32_t smem_u32(const void* p) {
    uint32_t a;
    asm("{ .reg .u64 t; cvta.to.shared.u64 t, %1; cvt.u32.u64 %0, t; }" : "=r"(a) : "l"(p));
    return a;
}

#define LDSM_X4(r0, r1, r2, r3, a) \
    asm volatile("ldmatrix.sync.aligned.m8n8.x4.shared.b16 {%0,%1,%2,%3}, [%4];" \
                 : "=r"(r0), "=r"(r1), "=r"(r2), "=r"(r3) : "r"(a))

#define LDSM_X4_T(r0, r1, r2, r3, a) \
    asm volatile("ldmatrix.sync.aligned.m8n8.x4.trans.shared.b16 {%0,%1,%2,%3}, [%4];" \
                 : "=r"(r0), "=r"(r1), "=r"(r2), "=r"(r3) : "r"(a))

#define MMA16816(d, a0, a1, a2, a3, b0, b1) \
    asm volatile("mma.sync.aligned.m16n8k16.row.col.f32.f16.f16.f32 " \
                 "{%0,%1,%2,%3}, {%4,%5,%6,%7}, {%8,%9}, {%0,%1,%2,%3};" \
                 : "+f"((d)[0]), "+f"((d)[1]), "+f"((d)[2]), "+f"((d)[3]) \
                 : "r"(a0), "r"(a1), "r"(a2), "r"(a3), "r"(b0), "r"(b1))

__device__ __forceinline__ float tanh_a(float x) {
    float r;
    asm("tanh.approx.f32 %0, %1;" : "=f"(r) : "f"(x));
    return r;
}
__device__ __forceinline__ float sigm_exact(float v) {
    float e = __expf(-v);
    return __fdividef(1.0f, 1.0f + e);
}

__global__ __launch_bounds__(NTHREADS, 1) void lstm_mma_kernel(
    const float* __restrict__ x,
    const float* __restrict__ Wih, const float* __restrict__ Whh,
    const float* __restrict__ bih, const float* __restrict__ bhh,
    const float* __restrict__ W1, const float* __restrict__ b1,
    const float* __restrict__ W2, const float* __restrict__ b2,
    float* __restrict__ out)
{
    extern __shared__ char smem[];
    const uint32_t sb = smem_u32(smem);
    const int tid  = threadIdx.x;
    const int wid  = tid >> 5;
    const int lane = tid & 31;
    const int b0   = blockIdx.x * ROWS;

    // ---- stage weights: packed row pr = u*4 + q  (orig row q*128+u) ----
    for (int i = tid; i < 512 * 96; i += NTHREADS) {
        int pr = i / 96;                  // packed row 0..511
        int kp = (i - pr * 96) * 2;       // 0..190 even
        int q = pr & 3, u = pr >> 2;
        int row = q * HDIM + u;           // original row
        int mt = pr >> 4, j = pr & 15;
        int kt = kp >> 4, kl = kp & 15;
        float2 v;
        if (kp < FDIM) v = *(const float2*)(Wih + row * FDIM + kp);
        else           v = *(const float2*)(Whh + row * HDIM + (kp - FDIM));
        uint32_t addr = (uint32_t)((mt * 12 + kt) * 512
                        + j * 32 + (((kl >> 3) ^ ((j >> 2) & 1)) << 4) + (kl & 7) * 2);
        *(__half2*)(smem + AW_OFF + addr) = __floats2half2_rn(v.x, v.y);
    }
    // zero h buffer 0 (h0 = 0)
    for (int i = tid; i < 1024; i += NTHREADS)
        ((uint32_t*)(smem + HB_OFF))[i] = 0;

    // ---- per-thread frag addressing ----
    const int s8 = lane >> 3, jj = lane & 7;
    const int Ja = ((s8 & 1) << 3) + jj;
    const uint32_t a_lane = (uint32_t)(Ja * 32 + ((((s8 >> 1)) ^ ((Ja >> 2) & 1)) << 4));
    const int kb = ((s8 & 1) << 3) + jj;
    const uint32_t b_lane = (uint32_t)(kb * 32 + ((((s8 >> 1)) ^ ((kb >> 2) & 1)) << 4));

    const int g  = lane >> 2;             // d-frag row 0..7
    const int cq = lane & 3;              // d-frag col pair
    const int q  = g & 3;                 // this lane's gate (pre-transpose)
    const int gh = lane >> 4;             // 0..1

    float bias[4];
#pragma unroll
    for (int s = 0; s < 4; s++) {
        int u_s = wid * 8 + (s >> 1) * 4 + (s & 1) * 2 + gh;
        bias[s] = bih[q * HDIM + u_s] + bhh[q * HDIM + u_s];
    }

    const int mt_c = q >> 1, rh_c = q & 1;
    const int u_c  = wid * 8 + mt_c * 4 + rh_c * 2 + gh;
    uint32_t h_wr[2];
#pragma unroll
    for (int nt = 0; nt < 2; nt++)
        h_wr[nt] = (uint32_t)(HB_OFF + u_c * 32 + ((nt ^ mt_c) << 4) + cq * 4);

    // x publish setup (threads 0..255)
    const int xrow = tid & 15, kq = (tid >> 4) & 15;
    const float* xptr = x + ((size_t)(b0 + xrow) * T_STEPS) * FDIM + kq * 4;
    uint32_t xs_addr[4];
#pragma unroll
    for (int i = 0; i < 4; i++) {
        int k = kq * 4 + i;
        xs_addr[i] = (uint32_t)(XB_OFF
            + k * 32 + (((xrow >> 3) ^ ((k >> 2) & 1)) << 4) + (xrow & 7) * 2);
    }

    __syncthreads();                      // weights staged

    // ---- preload W_hh A-frags (kt 4..11) for this warp's 2 m-tiles ----
    uint32_t ah[2][8][4];
#pragma unroll
    for (int mt = 0; mt < 2; mt++)
#pragma unroll
        for (int kt = 0; kt < 8; kt++)
            LDSM_X4(ah[mt][kt][0], ah[mt][kt][1], ah[mt][kt][2], ah[mt][kt][3],
                sb + AW_OFF + (uint32_t)(((wid * 2 + mt) * 12 + 4 + kt) * 512) + a_lane);

    float cs[4];
#pragma unroll
    for (int i = 0; i < 4; i++) cs[i] = 0.0f;

    // ---- prologue: publish x_0 (buf0), x_1 (buf1); prefetch x_2 ----
    float4 xr;
    if (tid < 256) {
        float4 x0 = *(const float4*)xptr;
        *(__half*)(smem + xs_addr[0]) = __float2half_rn(x0.x);
        *(__half*)(smem + xs_addr[1]) = __float2half_rn(x0.y);
        *(__half*)(smem + xs_addr[2]) = __float2half_rn(x0.z);
        *(__half*)(smem + xs_addr[3]) = __float2half_rn(x0.w);
        float4 x1 = *(const float4*)(xptr + FDIM);
        *(__half*)(smem + xs_addr[0] + 2048) = __float2half_rn(x1.x);
        *(__half*)(smem + xs_addr[1] + 2048) = __float2half_rn(x1.y);
        *(__half*)(smem + xs_addr[2] + 2048) = __float2half_rn(x1.z);
        *(__half*)(smem + xs_addr[3] + 2048) = __float2half_rn(x1.w);
        xr = *(const float4*)(xptr + 2 * FDIM);
    }
    __syncthreads();                      // x_0, x_1 visible

    // ---- initial D = bias + W_ih * x_0 (reads x buf 0) ----
    float D[2][8];
#pragma unroll
    for (int mt = 0; mt < 2; mt++)
#pragma unroll
        for (int nt = 0; nt < 2; nt++) {
            D[mt][nt * 4 + 0] = bias[mt * 2];     D[mt][nt * 4 + 1] = bias[mt * 2];
            D[mt][nt * 4 + 2] = bias[mt * 2 + 1]; D[mt][nt * 4 + 3] = bias[mt * 2 + 1];
        }
#pragma unroll
    for (int kt = 0; kt < 4; kt++) {
        uint32_t v0, v1, v2, v3;
        LDSM_X4_T(v0, v1, v2, v3, sb + XB_OFF + b_lane + kt * 512);
#pragma unroll
        for (int mt = 0; mt < 2; mt++) {
            uint32_t a0, a1, a2, a3;
            LDSM_X4(a0, a1, a2, a3,
                sb + AW_OFF + (uint32_t)(((wid * 2 + mt) * 12 + kt) * 512) + a_lane);
            MMA16816(&D[mt][0], a0, a1, a2, a3, v0, v1);
            MMA16816(&D[mt][4], a0, a1, a2, a3, v2, v3);
        }
    }
    __syncthreads();                      // x buf0 reads done before t=0 republish

    const int p0 = q & 1, p1 = q >> 1;    // lane position bits in 4-lane group

    for (int t = 0; t < T_STEPS; t++) {
        const uint32_t cur = (uint32_t)(t & 1);
        const uint32_t hb_cur = sb + HB_OFF + cur * 4096 + b_lane;

        // ---- 1. h part: kt 4..11, A from registers; D += W_hh h_{t-1} ----
#pragma unroll
        for (int kt = 0; kt < 8; kt++) {
            uint32_t v0, v1, v2, v3;
            LDSM_X4_T(v0, v1, v2, v3, hb_cur + kt * 512);
#pragma unroll
            for (int mt = 0; mt < 2; mt++) {
                MMA16816(&D[mt][0], ah[mt][kt][0], ah[mt][kt][1],
                         ah[mt][kt][2], ah[mt][kt][3], v0, v1);
                MMA16816(&D[mt][4], ah[mt][kt][0], ah[mt][kt][1],
                         ah[mt][kt][2], ah[mt][kt][3], v2, v3);
            }
        }

        // ---- 2. publish x_{t+2} into x buf cur (read by tail of t+1) ----
        if (tid < 256 && t + 2 < T_STEPS) {
            const uint32_t pb = cur * 2048u;
            *(__half*)(smem + xs_addr[0] + pb) = __float2half_rn(xr.x);
            *(__half*)(smem + xs_addr[1] + pb) = __float2half_rn(xr.y);
            *(__half*)(smem + xs_addr[2] + pb) = __float2half_rn(xr.z);
            *(__half*)(smem + xs_addr[3] + pb) = __float2half_rn(xr.w);
            if (t + 3 < T_STEPS) xr = *(const float4*)(xptr + (size_t)(t + 3) * FDIM);
        }

        // ---- 3. epilogue: activation on lane's gate q ----
        float v[4][4];
#pragma unroll
        for (int mt = 0; mt < 2; mt++)
#pragma unroll
            for (int nt = 0; nt < 2; nt++)
#pragma unroll
                for (int rh = 0; rh < 2; rh++)
#pragma unroll
                    for (int ci = 0; ci < 2; ci++) {
                        float d = D[mt][nt * 4 + rh * 2 + ci];
                        float a = (q == 2) ? d : 0.5f * d;
                        float th = tanh_a(a);
                        v[mt * 2 + rh][nt * 2 + ci] =
                            (q == 2) ? th : fmaf(th, 0.5f, 0.5f);
                    }

        // 4x4 lane-group transpose (gates -> cell owner)
#pragma unroll
        for (int s1 = 0; s1 < 2; s1++)
#pragma unroll
            for (int j = 0; j < 4; j++) {
                float a0 = v[s1 * 2][j], a1 = v[s1 * 2 + 1][j];
                float send = p0 ? a0 : a1;
                float got = __shfl_xor_sync(0xFFFFFFFFu, send, 4);
                v[s1 * 2][j]     = p0 ? got : a0;
                v[s1 * 2 + 1][j] = p0 ? a1 : got;
            }
#pragma unroll
        for (int s0 = 0; s0 < 2; s0++)
#pragma unroll
            for (int j = 0; j < 4; j++) {
                float a0 = v[s0][j], a1 = v[2 + s0][j];
                float send = p1 ? a0 : a1;
                float got = __shfl_xor_sync(0xFFFFFFFFu, send, 8);
                v[s0][j]     = p1 ? got : a0;
                v[2 + s0][j] = p1 ? a1 : got;
            }

        // cell update + h_t writeback into buf cur^1
        float hv[4];
#pragma unroll
        for (int j = 0; j < 4; j++) {
            cs[j] = v[1][j] * cs[j] + v[0][j] * v[2][j];
            hv[j] = v[3][j] * tanh_a(cs[j]);
        }
        const uint32_t nxt = (cur ^ 1u) * 4096u;
        *(__half2*)(smem + h_wr[0] + nxt) = __floats2half2_rn(hv[0], hv[1]);
        *(__half2*)(smem + h_wr[1] + nxt) = __floats2half2_rn(hv[2], hv[3]);
        if (t == T_STEPS - 1) {
#pragma unroll
            for (int j = 0; j < 4; j++) {
                int r = (j >> 1) * 8 + cq * 2 + (j & 1);
                *(float*)(smem + HS_OFF + (u_c * 16 + r) * 4) = hv[j];
            }
        }

        // ---- 4. tail: D = bias + W_ih x_{t+1} (x buf cur^1, from step t-1) ----
        if (t + 1 < T_STEPS) {
            const uint32_t xb_nxt = sb + XB_OFF + (cur ^ 1u) * 2048u + b_lane;
#pragma unroll
            for (int mt = 0; mt < 2; mt++)
#pragma unroll
                for (int nt = 0; nt < 2; nt++) {
                    D[mt][nt * 4 + 0] = bias[mt * 2];     D[mt][nt * 4 + 1] = bias[mt * 2];
                    D[mt][nt * 4 + 2] = bias[mt * 2 + 1]; D[mt][nt * 4 + 3] = bias[mt * 2 + 1];
                }
#pragma unroll
            for (int kt = 0; kt < 4; kt++) {
                uint32_t v0, v1, v2, v3;
                LDSM_X4_T(v0, v1, v2, v3, xb_nxt + kt * 512);
#pragma unroll
                for (int mt = 0; mt < 2; mt++) {
                    uint32_t a0, a1, a2, a3;
                    LDSM_X4(a0, a1, a2, a3,
                        sb + AW_OFF + (uint32_t)(((wid * 2 + mt) * 12 + kt) * 512) + a_lane);
                    MMA16816(&D[mt][0], a0, a1, a2, a3, v0, v1);
                    MMA16816(&D[mt][4], a0, a1, a2, a3, v2, v3);
                }
            }
        }

        // ---- 5. step barrier ----
        __syncthreads();
    }

    // ---- head: Linear(128,32) -> ReLU -> Linear(32,1) -> Sigmoid ----
    float* W1t = (float*)(smem + AW_OFF);
    float* zS  = (float*)(smem + HB_OFF);
    const float* hs = (const float*)(smem + HS_OFF);
    for (int i = tid; i < 32 * HDIM; i += NTHREADS) {
        int m = i >> 7, k = i & 127;
        W1t[k * 32 + m] = W1[i];
    }
    __syncthreads();
    {
        int m = tid & 31, r = (tid >> 5) & 15;
        float z = b1[m];
        for (int k = 0; k < HDIM; k++)
            z += hs[k * 16 + r] * W1t[k * 32 + m];
        zS[r * 32 + m] = fmaxf(z, 0.0f);
    }
    __syncthreads();
    if (tid < ROWS) {
        float ssum = b2[0];
#pragma unroll
        for (int mm = 0; mm < 32; mm++) ssum += zS[tid * 32 + mm] * W2[mm];
        out[b0 + tid] = sigm_exact(ssum);
    }
}

extern "C" void kernel_launch(void* const* d_in, const int* in_sizes, int n_in,
                              void* d_out, int out_size) {
    (void)in_sizes; (void)n_in; (void)out_size;
    const float* x   = (const float*)d_in[0];
    const float* Wih = (const float*)d_in[1];
    const float* Whh = (const float*)d_in[2];
    const float* bih = (const float*)d_in[3];
    const float* bhh = (const float*)d_in[4];
    const float* W1  = (const float*)d_in[5];
    const float* b1  = (const float*)d_in[6];
    const float* W2  = (const float*)d_in[7];
    const float* b2  = (const float*)d_in[8];
    float* out = (float*)d_out;

    cudaFuncSetAttribute(lstm_mma_kernel,
                         cudaFuncAttributeMaxDynamicSharedMemorySize, SMEM_TOTAL);
    lstm_mma_kernel<<<NBLOCKS, NTHREADS, SMEM_TOTAL>>>(
        x, Wih, Whh, bih, bhh, W1, b1, W2, b2, out);
}